// round 2
// baseline (speedup 1.0000x reference)
#include <cuda_runtime.h>
#include <cstdint>
#include <math_constants.h>

#define TPB 256
#define NCTAS 296

__device__ unsigned int g_counter;

__global__ void init_counter_kernel() { g_counter = 0u; }

__device__ __forceinline__ unsigned long long pk2(float lo, float hi) {
    unsigned long long r;
    asm("mov.b64 %0, {%1, %2};" : "=l"(r) : "f"(lo), "f"(hi));
    return r;
}
__device__ __forceinline__ void upk2(unsigned long long v, float& lo, float& hi) {
    asm("mov.b64 {%0, %1}, %2;" : "=f"(lo), "=f"(hi) : "l"(v));
}
// Packed fp32x2 FMA (Blackwell): per-lane IEEE rn FMA, identical rounding to scalar fmaf.
__device__ __forceinline__ unsigned long long ffma2(unsigned long long a,
                                                    unsigned long long b,
                                                    unsigned long long c) {
    unsigned long long d;
    asm("fma.rn.f32x2 %0, %1, %2, %3;" : "=l"(d) : "l"(a), "l"(b), "l"(c));
    return d;
}

__global__ __launch_bounds__(TPB, 2) void e8p_kernel(
    const float* __restrict__ X,
    const float* __restrict__ grid,       // [n_grid, 8]
    const float* __restrict__ gnorm,      // [n_grid]
    const int*   __restrict__ allcombo,   // [128, n_grid]
    const int*   __restrict__ idx_map,    // [256]
    float* __restrict__ out,
    int N, int n_grid, int idx_mode)
{
    extern __shared__ unsigned long long smem_u64[];
    unsigned long long* sgd = smem_u64;              // [n_grid*8] (g,g) duplicated pairs
    unsigned long long* snn = sgd + (size_t)n_grid * 8; // [n_grid] (-norm,-norm)
    int* simap = (int*)(snn + n_grid);               // [256]

    for (int i = threadIdx.x; i < n_grid * 8; i += TPB) {
        float g = grid[i];
        sgd[i] = pk2(g, g);
    }
    for (int i = threadIdx.x; i < n_grid; i += TPB) {
        float nn = -gnorm[i];
        snn[i] = pk2(nn, nn);
    }
    if (threadIdx.x < 256) simap[threadIdx.x] = idx_map[threadIdx.x];
    __syncthreads();

    const int nchunks = N >> 5;
    const int lane = threadIdx.x & 31;
    const unsigned long long ZERO = pk2(0.0f, 0.0f);
    const unsigned long long TWO  = pk2(2.0f, 2.0f);

    while (true) {
        unsigned c;
        if (lane == 0) c = atomicAdd(&g_counter, 1u);
        c = __shfl_sync(0xFFFFFFFFu, c, 0);
        if (c >= (unsigned)nchunks) break;
        const int row = (int)(c * 32u) + lane;

        const float4* X4 = (const float4*)(X + (size_t)row * 8);
        float4 xa = X4[0], xb = X4[1];
        float x[8] = {xa.x, xa.y, xa.z, xa.w, xb.x, xb.y, xb.z, xb.w};

        // Prologue: shifted vectors, sign masks, signed-abs packed as (p-lane, m-lane).
        float yp[8], ym[8];
        unsigned negp = 0u, negm = 0u;
        #pragma unroll
        for (int j = 0; j < 8; j++) {
            yp[j] = __fadd_rn(x[j], 0.25f);
            ym[j] = __fsub_rn(x[j], 0.25f);
            if (yp[j] < 0.0f) negp |= 1u << j;
            if (ym[j] < 0.0f) negm |= 1u << j;
        }
        const unsigned pp = __popc(negp) & 1u;
        const unsigned pm = __popc(negm) & 1u;

        unsigned long long ya[8];
        {
            float ap0 = fabsf(yp[0]); if (pp) ap0 = -ap0;
            float am0 = fabsf(ym[0]); if (pm) am0 = -am0;
            ya[0] = pk2(ap0, am0);
            #pragma unroll
            for (int j = 1; j < 8; j++) ya[j] = pk2(fabsf(yp[j]), fabsf(ym[j]));
        }

        // Brute-force argmax of s = fl(2*dot - norm), dot = sequential FMA chain
        // (ascending j, init 0) — replicates the reference's accumulation exactly,
        // both parts in the two f32x2 lanes.
        float bsp = -CUDART_INF_F, bsm = -CUDART_INF_F;
        int qp = 0, qm = 0;
        #pragma unroll 4
        for (int q = 0; q < n_grid; q++) {
            const ulonglong2* gpt = (const ulonglong2*)(sgd + (size_t)q * 8);
            ulonglong2 g01 = gpt[0], g23 = gpt[1], g45 = gpt[2], g67 = gpt[3];

            unsigned long long acc = ffma2(g01.x, ya[0], ZERO);
            acc = ffma2(g01.y, ya[1], acc);
            acc = ffma2(g23.x, ya[2], acc);
            acc = ffma2(g23.y, ya[3], acc);
            acc = ffma2(g45.x, ya[4], acc);
            acc = ffma2(g45.y, ya[5], acc);
            acc = ffma2(g67.x, ya[6], acc);
            acc = ffma2(g67.y, ya[7], acc);
            unsigned long long s2 = ffma2(TWO, acc, snn[q]);

            float sp, sm;
            upk2(s2, sp, sm);
            if (sp > bsp) { bsp = sp; qp = q; }
            if (sm > bsm) { bsm = sm; qm = q; }
        }

        // Direct residuals, reference rounding: d = fl(y - v), sq = fl(d*d),
        // sum ascending with separate adds, then IEEE sqrt.
        const unsigned mnegp = negp ^ pp;   // parity flips bit 0
        const unsigned mnegm = negm ^ pm;
        float e2p = 0.0f, e2m = 0.0f;
        #pragma unroll
        for (int j = 0; j < 8; j++) {
            float gp_ = ((const float*)(sgd + (size_t)qp * 8 + j))[0];
            float gm_ = ((const float*)(sgd + (size_t)qm * 8 + j))[0];
            float vpj = ((mnegp >> j) & 1u) ? -gp_ : gp_;
            float vmj = ((mnegm >> j) & 1u) ? -gm_ : gm_;
            float dp = __fsub_rn(yp[j], vpj);
            float dm = __fsub_rn(ym[j], vmj);
            e2p = __fadd_rn(e2p, __fmul_rn(dp, dp));
            e2m = __fadd_rn(e2m, __fmul_rn(dm, dm));
        }
        const bool which = __fsqrt_rn(e2p) < __fsqrt_rn(e2m);

        const int q = which ? qp : qm;
        const unsigned mneg = which ? mnegp : mnegm;
        const float delta = which ? -0.25f : 0.25f;

        const int mint = (int)(__brev(mneg & 0xFFu) >> 24);  // bit j -> weight 2^(7-j)
        const int r128 = simap[mint];
        const int ridx = __ldg(&allcombo[(size_t)r128 * n_grid + q]);
        const int fidx = which ? ridx : (ridx - 32768);

        float v[8];
        #pragma unroll
        for (int j = 0; j < 8; j++) {
            float g = ((const float*)(sgd + (size_t)q * 8 + j))[0];
            float sg = ((mneg >> j) & 1u) ? -g : g;     // grid*mask (exact)
            v[j] = __fadd_rn(sg, delta);                // fl(vals -/+ 0.25)
        }
        float4* O = (float4*)(out + (size_t)row * 8);
        O[0] = make_float4(v[0], v[1], v[2], v[3]);
        O[1] = make_float4(v[4], v[5], v[6], v[7]);

        if (idx_mode == 1) {
            out[(size_t)N * 8 + row] = (float)fidx;                 // idx as float
        } else if (idx_mode == 2) {
            ((short*)(out + (size_t)N * 8))[row] = (short)fidx;     // idx as packed int16
        }
    }
}

extern "C" void kernel_launch(void* const* d_in, const int* in_sizes, int n_in,
                              void* d_out, int out_size) {
    const float* X        = (const float*)d_in[0];
    const float* grid     = (const float*)d_in[1];
    const float* gnorm    = (const float*)d_in[2];
    const int*   allcombo = (const int*)d_in[3];
    const int*   idx_map  = (const int*)d_in[4];

    const int N = in_sizes[0] / 8;
    const int n_grid = in_sizes[2];

    int idx_mode = 0;
    if (out_size >= N * 9) idx_mode = 1;                 // idx stored as float elems
    else if (out_size >= N * 8 + (N + 1) / 2) idx_mode = 2;  // idx packed as int16

    size_t smem_bytes = (size_t)n_grid * 8 * 8 + (size_t)n_grid * 8 + 1024 + 64;
    cudaFuncSetAttribute(e8p_kernel, cudaFuncAttributeMaxDynamicSharedMemorySize,
                         (int)smem_bytes);

    init_counter_kernel<<<1, 1>>>();
    e8p_kernel<<<NCTAS, TPB, smem_bytes>>>(X, grid, gnorm, allcombo, idx_map,
                                           (float*)d_out, N, n_grid, idx_mode);
}

// round 3
// speedup vs baseline: 1.1027x; 1.1027x over previous
#include <cuda_runtime.h>
#include <cstdint>
#include <math_constants.h>

#define TPB 256
#define NCTAS 296

__device__ unsigned int g_counter;

__global__ void init_counter_kernel() { g_counter = 0u; }

__device__ __forceinline__ unsigned long long pk2(float lo, float hi) {
    unsigned long long r;
    asm("mov.b64 %0, {%1, %2};" : "=l"(r) : "f"(lo), "f"(hi));
    return r;
}
__device__ __forceinline__ void upk2(unsigned long long v, float& lo, float& hi) {
    asm("mov.b64 {%0, %1}, %2;" : "=f"(lo), "=f"(hi) : "l"(v));
}
// Packed fp32x2 FMA (Blackwell): per-lane IEEE rn FMA, identical rounding to scalar fmaf.
__device__ __forceinline__ unsigned long long ffma2(unsigned long long a,
                                                    unsigned long long b,
                                                    unsigned long long c) {
    unsigned long long d;
    asm("fma.rn.f32x2 %0, %1, %2, %3;" : "=l"(d) : "l"(a), "l"(b), "l"(c));
    return d;
}

__global__ __launch_bounds__(TPB, 2) void e8p_kernel(
    const float* __restrict__ X,
    const float* __restrict__ grid,       // [n_grid, 8]
    const float* __restrict__ gnorm,      // [n_grid]
    const int*   __restrict__ allcombo,   // [128, n_grid]
    const int*   __restrict__ idx_map,    // [256]
    float* __restrict__ out,
    int N, int n_grid, int idx_mode)
{
    // Candidate record: 5 ulonglong2 = 80 B:
    //   [0..3] = (g0,g0),(g1,g1) | (g2,g2),(g3,g3) | (g4,g4),(g5,g5) | (g6,g6),(g7,g7)
    //   [4]    = (-norm,-norm), pad
    extern __shared__ ulonglong2 srec[];
    int* simap = (int*)(srec + (size_t)n_grid * 5);   // [256]

    for (int q = threadIdx.x; q < n_grid; q += TPB) {
        const float* g = grid + (size_t)q * 8;
        ulonglong2* r = srec + (size_t)q * 5;
        #pragma unroll
        for (int p = 0; p < 4; p++)
            r[p] = make_ulonglong2(pk2(g[2 * p], g[2 * p]),
                                   pk2(g[2 * p + 1], g[2 * p + 1]));
        float nn = -gnorm[q];
        r[4] = make_ulonglong2(pk2(nn, nn), 0ull);
    }
    if (threadIdx.x < 256) simap[threadIdx.x] = idx_map[threadIdx.x];
    __syncthreads();

    const int nchunks = N >> 6;          // 64 rows per chunk (2 per lane)
    const int lane = threadIdx.x & 31;
    const unsigned long long ZERO = pk2(0.0f, 0.0f);
    const unsigned long long TWO  = pk2(2.0f, 2.0f);
    const float* sgf = (const float*)srec;   // g_j of candidate q at sgf[q*20 + j*2]

    while (true) {
        unsigned c;
        if (lane == 0) c = atomicAdd(&g_counter, 1u);
        c = __shfl_sync(0xFFFFFFFFu, c, 0);
        if (c >= (unsigned)nchunks) break;
        const int base = (int)(c << 6);
        int rows[2] = {base + lane, base + 32 + lane};

        float x[2][8];
        unsigned negp[2], negm[2], pp[2], pm[2];
        unsigned long long ya[2][8];

        #pragma unroll
        for (int r = 0; r < 2; r++) {
            const float4* X4 = (const float4*)(X + (size_t)rows[r] * 8);
            float4 xa = X4[0], xb = X4[1];
            float* xr = x[r];
            xr[0]=xa.x; xr[1]=xa.y; xr[2]=xa.z; xr[3]=xa.w;
            xr[4]=xb.x; xr[5]=xb.y; xr[6]=xb.z; xr[7]=xb.w;

            unsigned np = 0u, nm = 0u;
            float ap[8], am[8];
            #pragma unroll
            for (int j = 0; j < 8; j++) {
                float yp = __fadd_rn(xr[j], 0.25f);
                float ym = __fsub_rn(xr[j], 0.25f);
                if (yp < 0.0f) np |= 1u << j;
                if (ym < 0.0f) nm |= 1u << j;
                ap[j] = fabsf(yp);
                am[j] = fabsf(ym);
            }
            pp[r] = __popc(np) & 1u;
            pm[r] = __popc(nm) & 1u;
            negp[r] = np; negm[r] = nm;
            if (pp[r]) ap[0] = -ap[0];
            if (pm[r]) am[0] = -am[0];
            #pragma unroll
            for (int j = 0; j < 8; j++) ya[r][j] = pk2(ap[j], am[j]);
        }

        // Brute-force argmax of s = fl(2*dot - norm); dot = sequential FMA chain
        // (ascending j, init 0) in the two f32x2 lanes (p-shift, m-shift).
        float bsp[2] = {-CUDART_INF_F, -CUDART_INF_F};
        float bsm[2] = {-CUDART_INF_F, -CUDART_INF_F};
        int qp[2] = {0, 0}, qm[2] = {0, 0};

        #pragma unroll 2
        for (int q = 0; q < n_grid; q++) {
            const ulonglong2* gpt = srec + (size_t)q * 5;
            ulonglong2 g01 = gpt[0], g23 = gpt[1], g45 = gpt[2], g67 = gpt[3];
            unsigned long long nn = gpt[4].x;

            #pragma unroll
            for (int r = 0; r < 2; r++) {
                unsigned long long acc = ffma2(g01.x, ya[r][0], ZERO);
                acc = ffma2(g01.y, ya[r][1], acc);
                acc = ffma2(g23.x, ya[r][2], acc);
                acc = ffma2(g23.y, ya[r][3], acc);
                acc = ffma2(g45.x, ya[r][4], acc);
                acc = ffma2(g45.y, ya[r][5], acc);
                acc = ffma2(g67.x, ya[r][6], acc);
                acc = ffma2(g67.y, ya[r][7], acc);
                unsigned long long s2 = ffma2(TWO, acc, nn);

                float sp, sm;
                upk2(s2, sp, sm);
                if (sp > bsp[r]) { bsp[r] = sp; qp[r] = q; }
                if (sm > bsm[r]) { bsm[r] = sm; qm[r] = q; }
            }
        }

        // Epilogue per row: direct residuals with reference rounding.
        #pragma unroll
        for (int r = 0; r < 2; r++) {
            const unsigned mnegp = negp[r] ^ pp[r];   // parity flips bit 0
            const unsigned mnegm = negm[r] ^ pm[r];
            float e2p = 0.0f, e2m = 0.0f;
            #pragma unroll
            for (int j = 0; j < 8; j++) {
                float yp = __fadd_rn(x[r][j], 0.25f);
                float ym = __fsub_rn(x[r][j], 0.25f);
                float gp_ = sgf[qp[r] * 20 + j * 2];
                float gm_ = sgf[qm[r] * 20 + j * 2];
                float vpj = ((mnegp >> j) & 1u) ? -gp_ : gp_;
                float vmj = ((mnegm >> j) & 1u) ? -gm_ : gm_;
                float dp = __fsub_rn(yp, vpj);
                float dm = __fsub_rn(ym, vmj);
                e2p = __fadd_rn(e2p, __fmul_rn(dp, dp));
                e2m = __fadd_rn(e2m, __fmul_rn(dm, dm));
            }
            const bool which = __fsqrt_rn(e2p) < __fsqrt_rn(e2m);

            const int q = which ? qp[r] : qm[r];
            const unsigned mneg = which ? mnegp : mnegm;
            const float delta = which ? -0.25f : 0.25f;

            const int mint = (int)(__brev(mneg & 0xFFu) >> 24);  // bit j -> 2^(7-j)
            const int r128 = simap[mint];
            const int ridx = __ldg(&allcombo[(size_t)r128 * n_grid + q]);
            const int fidx = which ? ridx : (ridx - 32768);

            float v[8];
            #pragma unroll
            for (int j = 0; j < 8; j++) {
                float g = sgf[q * 20 + j * 2];
                float sg = ((mneg >> j) & 1u) ? -g : g;    // grid*mask (exact)
                v[j] = __fadd_rn(sg, delta);               // fl(vals -/+ 0.25)
            }
            float4* O = (float4*)(out + (size_t)rows[r] * 8);
            O[0] = make_float4(v[0], v[1], v[2], v[3]);
            O[1] = make_float4(v[4], v[5], v[6], v[7]);

            if (idx_mode == 1) {
                out[(size_t)N * 8 + rows[r]] = (float)fidx;
            } else if (idx_mode == 2) {
                ((short*)(out + (size_t)N * 8))[rows[r]] = (short)fidx;
            }
        }
    }
}

extern "C" void kernel_launch(void* const* d_in, const int* in_sizes, int n_in,
                              void* d_out, int out_size) {
    const float* X        = (const float*)d_in[0];
    const float* grid     = (const float*)d_in[1];
    const float* gnorm    = (const float*)d_in[2];
    const int*   allcombo = (const int*)d_in[3];
    const int*   idx_map  = (const int*)d_in[4];

    const int N = in_sizes[0] / 8;
    const int n_grid = in_sizes[2];

    int idx_mode = 0;
    if (out_size >= N * 9) idx_mode = 1;                     // idx stored as floats
    else if (out_size >= N * 8 + (N + 1) / 2) idx_mode = 2;  // idx packed as int16

    size_t smem_bytes = (size_t)n_grid * 80 + 1024 + 64;
    cudaFuncSetAttribute(e8p_kernel, cudaFuncAttributeMaxDynamicSharedMemorySize,
                         (int)smem_bytes);

    init_counter_kernel<<<1, 1>>>();
    e8p_kernel<<<NCTAS, TPB, smem_bytes>>>(X, grid, gnorm, allcombo, idx_map,
                                           (float*)d_out, N, n_grid, idx_mode);
}